// round 12
// baseline (speedup 1.0000x reference)
#include <cuda_runtime.h>
#include <cuda_bf16.h>

// ---------------------------------------------------------------------------
// DynamicDWConv — Round 12: instruction-count attack.
// R11 falsified the occupancy theory (occ 25->50%, issue stuck at 45%, K1
// slower). Both conv kernels sit ~4x above their FMA floor at two different
// occupancies -> stream-volume-bound. This round: 2-column x-blocking with
// aligned float2 smem loads (3.3x fewer LDS instrs) + packed fma.rn.f32x2
// (half the FMA instrs, sm_103a FFMA2). K1 back to 512 threads (measured
// faster than 1024).
// ---------------------------------------------------------------------------

#define BATCH 8
#define CH    64
#define HW    256
#define BC    (BATCH * CH)       // 512
#define KK    25

__device__ float g_pool[BC];            // global-avg-pool result
__device__ float g_kern[BC * KK];       // dynamic kernels, [bc][25]

// ---------------- packed f32x2 helpers (sm_103a) ----------------------------
__device__ __forceinline__ unsigned long long pk2(float lo, float hi) {
    unsigned long long r;
    asm("mov.b64 %0, {%1, %2};" : "=l"(r) : "f"(lo), "f"(hi));
    return r;
}
__device__ __forceinline__ unsigned long long fma2(unsigned long long a,
                                                   unsigned long long b,
                                                   unsigned long long c) {
    unsigned long long d;
    asm("fma.rn.f32x2 %0, %1, %2, %3;" : "=l"(d) : "l"(a), "l"(b), "l"(c));
    return d;
}

// ---------------- K1: plane pipeline ---------------------------------------
#define S1 132
#define S2 68
#define A_OFF 0
#define B_OFF (S1*S1)
#define C_OFF (2*S1*S1)
#define D_OFF (2*S1*S1 + S2*S2)
#define W_OFF (2*S1*S1 + 2*S2*S2)       // two 32-float weight slots
#define SMEM1_FLOATS (W_OFF + 64)
#define NT1 512                   // K1 threads (measured faster than 1024)

// Packed depthwise 5x5 conv: each thread owns TWO adjacent output columns.
// Aligned float2 loads (3 per row cover 6 input cols), 2 repacks build the
// odd-shift pairs, FFMA2 accumulates both columns at once.
// W x W plane, halo-2 buffer of row stride S (S even). Weights from smem.
template<int W, int S, int NT>
__device__ __forceinline__ void dwconv5p(const float* __restrict__ src,
                                         float* __restrict__ dst,
                                         const float* __restrict__ swt,
                                         float bias_v) {
    constexpr int NP  = W / 2;                 // column pairs per row
    constexpr int NG  = NT / NP;               // thread groups in y
    constexpr int RPG = W / NG;                // rows per group
    constexpr int YB  = (RPG >= 8) ? 8 : RPG;  // y-block rows
    constexpr int NYB = RPG / YB;
    const int t  = threadIdx.x;
    const int tp = t % NP;
    const int g  = t / NP;
    const int cb = 2 * tp;                     // src col index of output pair

    // pack all 25 weights (both lanes identical)
    unsigned long long wp[KK];
#pragma unroll
    for (int i = 0; i < KK; i++) wp[i] = pk2(swt[i], swt[i]);
    const unsigned long long bp = pk2(bias_v, bias_v);

#pragma unroll
    for (int yb = 0; yb < NYB; yb++) {
        const int y0 = g * RPG + yb * YB;
        unsigned long long acc[YB];
#pragma unroll
        for (int i = 0; i < YB; i++) acc[i] = bp;     // bias pre-loaded
#pragma unroll
        for (int r = 0; r < YB + 4; r++) {
            const float2* rp = (const float2*)(src + (y0 + r) * S + cb);
            const float2 a = rp[0], b = rp[1], c = rp[2];
            unsigned long long q[5];
            q[0] = pk2(a.x, a.y);      // dx=0
            q[1] = pk2(a.y, b.x);      // dx=1
            q[2] = pk2(b.x, b.y);      // dx=2
            q[3] = pk2(b.y, c.x);      // dx=3
            q[4] = pk2(c.x, c.y);      // dx=4
#pragma unroll
            for (int dy = 0; dy < 5; dy++) {
                const int oy = r - dy;
                if (oy >= 0 && oy < YB) {
#pragma unroll
                    for (int dx = 0; dx < 5; dx++)
                        acc[oy] = fma2(q[dx], wp[dy * 5 + dx], acc[oy]);
                }
            }
        }
#pragma unroll
        for (int oy = 0; oy < YB; oy++)
            *(unsigned long long*)(dst + (y0 + oy + 2) * S + cb + 2) = acc[oy];
    }
}

__global__ __launch_bounds__(NT1, 1)
void k1_plane_pipeline(const float* __restrict__ x,
                       const float* __restrict__ w1,
                       const float* __restrict__ b1,
                       const float* __restrict__ w2,
                       const float* __restrict__ b2) {
    extern __shared__ float sm[];
    float* sA  = sm + A_OFF;
    float* sB  = sm + B_OFF;
    float* sC  = sm + C_OFF;
    float* sD  = sm + D_OFF;
    float* sw0 = sm + W_OFF;        // weight slot 0 (convs 1,3,5)
    float* sw1 = sm + W_OFF + 32;   // weight slot 1 (convs 2,4,6)

    const int bc = blockIdx.x;
    const int c  = bc & (CH - 1);
    const int t  = threadIdx.x;
    const float* plane = x + (size_t)bc * HW * HW;

    // zero data buffers (halos must be zero); stage conv1 weights
    for (int j = t; j < W_OFF; j += NT1) sm[j] = 0.f;
    if (t < KK) sw0[t] = w1[(0 * CH + c) * KK + t];          // c1
    __syncthreads();

    // avgpool 2x2: 256^2 -> 128^2 into sA interior; stage c2 concurrently
    for (int i = t; i < 128 * 128; i += NT1) {
        const int oy = i >> 7, ox = i & 127;
        const float2* r0 = (const float2*)(plane + (2 * oy)     * HW);
        const float2* r1 = (const float2*)(plane + (2 * oy + 1) * HW);
        const float2 a = r0[ox], b = r1[ox];
        sA[(oy + 2) * S1 + ox + 2] = (a.x + a.y + b.x + b.y) * 0.25f;
    }
    if (t < KK) sw1[t] = w1[(1 * CH + c) * KK + t];          // c2
    __syncthreads();

    dwconv5p<128, S1, NT1>(sA, sB, sw0, b1[0 * CH + c]);     // c1 reads sw0
    __syncthreads();
    if (t < KK) sw0[t] = w1[(2 * CH + c) * KK + t];          // c3 (c2 reads sw1)
    dwconv5p<128, S1, NT1>(sB, sA, sw1, b1[1 * CH + c]);     // c2 reads sw1
    __syncthreads();
    if (t < KK) sw1[t] = w2[(0 * CH + c) * KK + t];          // c4 (c3 reads sw0)
    dwconv5p<128, S1, NT1>(sA, sB, sw0, b1[2 * CH + c]);     // c3 reads sw0
    __syncthreads();

    // maxpool 2x2: 128^2 -> 64^2 into sC interior; stage c5 concurrently
    if (t < KK) sw0[t] = w2[(1 * CH + c) * KK + t];          // c5 (pool: no weights)
    for (int i = t; i < 64 * 64; i += NT1) {
        const int oy = i >> 6, ox = i & 63;
        const float* p = sB + (2 * oy + 2) * S1 + (2 * ox + 2);
        float m = fmaxf(fmaxf(p[0], p[1]), fmaxf(p[S1], p[S1 + 1]));
        sC[(oy + 2) * S2 + ox + 2] = m;
    }
    __syncthreads();

    dwconv5p<64, S2, NT1>(sC, sD, sw1, b2[0 * CH + c]);      // c4 reads sw1
    __syncthreads();
    if (t < KK) sw1[t] = w2[(2 * CH + c) * KK + t];          // c6 (c5 reads sw0)
    dwconv5p<64, S2, NT1>(sD, sC, sw0, b2[1 * CH + c]);      // c5 reads sw0
    __syncthreads();
    dwconv5p<64, S2, NT1>(sC, sD, sw1, b2[2 * CH + c]);      // c6 reads sw1
    __syncthreads();

    // global mean of sD interior (64x64)
    float s = 0.f;
    for (int i = t; i < 64 * 64; i += NT1) {
        const int oy = i >> 6, ox = i & 63;
        s += sD[(oy + 2) * S2 + ox + 2];
    }
#pragma unroll
    for (int off = 16; off > 0; off >>= 1)
        s += __shfl_down_sync(0xffffffffu, s, off);
    if ((t & 31) == 0) sA[t >> 5] = s;   // NT1/32 = 16 partials; sA free now
    __syncthreads();
    if (t == 0) {
        float tot = 0.f;
#pragma unroll
        for (int wnum = 0; wnum < NT1 / 32; wnum++) tot += sA[wnum];
        g_pool[bc] = tot * (1.f / 4096.f);
    }
}

// ---------------- K2: kernel generation ------------------------------------
__global__ void k2_make_kernels(const float* __restrict__ wk,
                                const float* __restrict__ bk) {
    const int idx = blockIdx.x * blockDim.x + threadIdx.x;
    if (idx >= BATCH * CH * KK) return;
    const int b = idx / (CH * KK);
    const int o = idx - b * (CH * KK);
    const float* gr = g_pool + b * CH;
    const float* wr = wk + (size_t)o * CH;
    float acc = bk[o];
#pragma unroll 8
    for (int c = 0; c < CH; c++) acc = fmaf(gr[c], wr[c], acc);
    g_kern[idx] = acc;
}

// ---------------- K3: dynamic depthwise conv on full res -------------------
#define TH 32                 // tile rows
#define TS 260                // tile row stride (256 + 4 halo), even
__global__ __launch_bounds__(256, 2)
void k3_dyn_conv(const float* __restrict__ x,
                 const float* __restrict__ bias,
                 float* __restrict__ out) {
    __shared__ __align__(16) float tile[(TH + 4) * TS];  // 36 x 260 = 37.4 KB
    __shared__ float sw[32];                             // dynamic 5x5 weights
    const int bc = blockIdx.y;
    const int ch = bc & (CH - 1);
    const int y0 = blockIdx.x * TH;
    const int t  = threadIdx.x;
    const float* plane = x + (size_t)bc * HW * HW;
    float*       po    = out + (size_t)bc * HW * HW;

    if (t < KK) sw[t] = g_kern[bc * KK + t];

    // load tile with halo (zero-pad outside image)
    for (int j = t; j < (TH + 4) * TS; j += 256) {
        const int r  = j / TS;
        const int cc = j - r * TS;
        const int gy = y0 - 2 + r;
        const int gx = cc - 2;
        float v = 0.f;
        if (gy >= 0 && gy < HW && gx >= 0 && gx < HW)
            v = plane[gy * HW + gx];
        tile[j] = v;
    }
    const float bias_v = bias[ch];
    __syncthreads();

    // 2-column packed conv: 256 threads = 128 pairs x 2 groups, RPG=16,
    // two 8-row y-blocks per thread.
    const int tp = t & 127;          // pair index  -> output cols 2tp, 2tp+1
    const int g  = t >> 7;           // group 0/1   -> rows [g*16, g*16+16)
    const int cb = 2 * tp;

    unsigned long long wp[KK];
#pragma unroll
    for (int i = 0; i < KK; i++) wp[i] = pk2(sw[i], sw[i]);
    const unsigned long long bp = pk2(bias_v, bias_v);

#pragma unroll
    for (int yb = 0; yb < 2; yb++) {
        const int r0 = g * 16 + yb * 8;        // tile-row base of this block
        unsigned long long acc[8];
#pragma unroll
        for (int i = 0; i < 8; i++) acc[i] = bp;
#pragma unroll
        for (int r = 0; r < 12; r++) {
            const float2* rp = (const float2*)(tile + (r0 + r) * TS + cb);
            const float2 a = rp[0], b = rp[1], c = rp[2];
            unsigned long long q[5];
            q[0] = pk2(a.x, a.y);
            q[1] = pk2(a.y, b.x);
            q[2] = pk2(b.x, b.y);
            q[3] = pk2(b.y, c.x);
            q[4] = pk2(c.x, c.y);
#pragma unroll
            for (int dy = 0; dy < 5; dy++) {
                const int oy = r - dy;
                if (oy >= 0 && oy < 8) {
#pragma unroll
                    for (int dx = 0; dx < 5; dx++)
                        acc[oy] = fma2(q[dx], wp[dy * 5 + dx], acc[oy]);
                }
            }
        }
#pragma unroll
        for (int oy = 0; oy < 8; oy++)
            *(unsigned long long*)(po + (y0 + r0 + oy) * HW + cb) = acc[oy];
    }
}

// ---------------- launch ----------------------------------------------------
extern "C" void kernel_launch(void* const* d_in, const int* in_sizes, int n_in,
                              void* d_out, int out_size) {
    const float* x    = (const float*)d_in[0];
    const float* w1   = (const float*)d_in[1];
    const float* b1   = (const float*)d_in[2];
    const float* w2   = (const float*)d_in[3];
    const float* b2   = (const float*)d_in[4];
    const float* wk   = (const float*)d_in[5];
    const float* bk   = (const float*)d_in[6];
    const float* bias = (const float*)d_in[7];
    float* out = (float*)d_out;

    // unconditional (idempotent, capture-safe): no static guards allowed
    cudaFuncSetAttribute(k1_plane_pipeline,
                         cudaFuncAttributeMaxDynamicSharedMemorySize,
                         SMEM1_FLOATS * (int)sizeof(float));

    k1_plane_pipeline<<<BC, NT1, SMEM1_FLOATS * sizeof(float)>>>(x, w1, b1, w2, b2);
    k2_make_kernels<<<(BATCH * CH * KK + 255) / 256, 256>>>(wk, bk);
    dim3 g3(HW / TH, BC);
    k3_dyn_conv<<<g3, 256>>>(x, bias, out);
}